// round 11
// baseline (speedup 1.0000x reference)
#include <cuda_runtime.h>

// Problem constants (fixed by the reference setup_inputs)
#define BB 8
#define DD 64
#define KK 32
#define HW 3136          // 56*56
#define LOG2E 1.4426950408889634f

// Scratch (allocation-free rule: __device__ globals)
__device__ float g_EM[BB * DD];

__device__ __forceinline__ float fast_ex2(float x) {
    float y;
    asm("ex2.approx.ftz.f32 %0, %1;" : "=f"(y) : "f"(x));
    return y;
}
__device__ __forceinline__ float fast_rcp(float x) {
    float y;
    asm("rcp.approx.ftz.f32 %0, %1;" : "=f"(y) : "f"(x));
    return y;
}

// Kernel 1: per (b,d) pair, compute E[b,d,n] = sum_k softmax_k(scale*r^2)*r
// and EM[b,d] = (1/K) * sum_n E[b,d,n].
// scale <= 0 everywhere => all softmax logits <= 0 => no max-subtraction needed.
__global__ __launch_bounds__(256) void enc_main_kernel(
    const float* __restrict__ X,          // (B, D, HW)
    const float* __restrict__ codewords,  // (K, D)
    const float* __restrict__ scale,      // (K, D)
    float* __restrict__ outE)             // (B, D, HW) -> written into d_out
{
    const int bd = blockIdx.x;            // b*DD + d
    const int d  = bd & (DD - 1);
    const float* __restrict__ xp = X    + (size_t)bd * HW;
    float* __restrict__       ep = outE + (size_t)bd * HW;

    // Per-d constants in registers (k fully unrolled below)
    float c[KK], s[KK];
#pragma unroll
    for (int k = 0; k < KK; k++) {
        c[k] = codewords[k * DD + d];
        s[k] = scale[k * DD + d] * LOG2E;   // pre-scale into log2 domain
    }

    float local = 0.0f;
    for (int n = threadIdx.x; n < HW; n += 256) {
        const float x = xp[n];
        float den = 0.0f, num = 0.0f;
#pragma unroll
        for (int k = 0; k < KK; k++) {
            float r  = x - c[k];
            float u  = s[k] * r;
            float v  = u * r;              // v = log2e * scale * r^2  (<= 0)
            float e2 = fast_ex2(v);        // exp(scale*r^2)
            den += e2;
            num = fmaf(e2, r, num);
        }
        float e = num * fast_rcp(den);
        ep[n] = e;
        local += e;
    }

    // Block reduction for EM
    __shared__ float red[256];
    red[threadIdx.x] = local;
    __syncthreads();
#pragma unroll
    for (int off = 128; off > 0; off >>= 1) {
        if (threadIdx.x < off) red[threadIdx.x] += red[threadIdx.x + off];
        __syncthreads();
    }
    if (threadIdx.x == 0) g_EM[bd] = red[0] * (1.0f / (float)KK);
}

// Kernel 2: per (b,d) pair, compute gamma[b,d] = sigmoid(EM[b,:] . fc_w[d,:] + fc_b[d])
// (the 64-wide dot is trivially cheap, so it's recomputed per block to save a launch),
// then out = relu(E * (1 + gamma)) in place.
__global__ __launch_bounds__(256) void enc_finalize_kernel(
    const float* __restrict__ fc_w,   // (D, D)
    const float* __restrict__ fc_b,   // (D,)
    float* __restrict__ out)          // (B, D, HW), holds E on input
{
    const int bd = blockIdx.x;
    const int b  = bd >> 6;           // / DD
    const int d  = bd & (DD - 1);
    const int t  = threadIdx.x;

    __shared__ float sh[DD];
    __shared__ float s_gm;

    if (t < DD) sh[t] = g_EM[b * DD + t] * fc_w[d * DD + t];
    __syncthreads();
    if (t == 0) {
        float acc = fc_b[d];
#pragma unroll
        for (int j = 0; j < DD; j++) acc += sh[j];
        float g = 1.0f / (1.0f + __expf(-acc));   // sigmoid
        s_gm = 1.0f + g;
    }
    __syncthreads();
    const float gm = s_gm;

    float4* __restrict__ p = (float4*)(out + (size_t)bd * HW);
    const int n4 = HW / 4;            // 3136 % 4 == 0
    for (int i = t; i < n4; i += 256) {
        float4 v = p[i];
        v.x = fmaxf(v.x * gm, 0.0f);
        v.y = fmaxf(v.y * gm, 0.0f);
        v.z = fmaxf(v.z * gm, 0.0f);
        v.w = fmaxf(v.w * gm, 0.0f);
        p[i] = v;
    }
}

extern "C" void kernel_launch(void* const* d_in, const int* in_sizes, int n_in,
                              void* d_out, int out_size) {
    const float* X    = (const float*)d_in[0];
    const float* cw   = (const float*)d_in[1];
    const float* sc   = (const float*)d_in[2];
    const float* fc_w = (const float*)d_in[3];
    const float* fc_b = (const float*)d_in[4];
    float* out = (float*)d_out;

    enc_main_kernel<<<BB * DD, 256>>>(X, cw, sc, out);
    enc_finalize_kernel<<<BB * DD, 256>>>(fc_w, fc_b, out);
}